// round 2
// baseline (speedup 1.0000x reference)
#include <cuda_runtime.h>
#include <math.h>

#define TPB 256
#define RQS_BOUND 5.0f
#define NEG_HALF_LOG_2PI (-0.9189385332046727f)

// ---- shared memory layout (float offsets) ----
// weights region (reused: encoder phase, then per-flow-transform)
#define OW1   0      // enc_W1 22x64
#define OB1   1408
#define OG1   1472
#define OBB1  1536
#define OW2   1600   // enc_W2 64x64
#define OB2   5696
#define OG2   5760
#define OBB2  5824
#define OW3   5888   // enc_W3 64x32
#define OB3   7936   // 32
// flow phase overlays the same region
#define FW1   0      // 33x64 = 2112
#define FB1   2112   // 64
#define FW2   2176   // 64x64 = 4096
#define FB2   6272   // 64
#define FW3   6336   // 64x24 (padded from 23) = 1536
#define FB3   7872   // 23
#define CTXOFF  8064           // 33 * TPB = 8448
#define WORKOFF (8064 + 33*TPB) // 64 * TPB = 16384
#define SMEM_FLOATS (WORKOFF + 64*TPB)

__device__ double g_partial[16384];

static __device__ __forceinline__ float softplusf(float x) {
    return fmaxf(x, 0.0f) + log1pf(expf(-fabsf(x)));
}
static __device__ __forceinline__ float gelu_exact(float x) {
    return x * normcdff(x);   // 0.5*x*(1+erf(x/sqrt(2)))
}

#define LN_GELU(h, GO, BO)                                              \
    do {                                                                \
        float mu = 0.0f;                                                \
        _Pragma("unroll")                                               \
        for (int j = 0; j < 64; j++) mu += (h)[j];                      \
        mu *= (1.0f / 64.0f);                                           \
        float var = 0.0f;                                               \
        _Pragma("unroll")                                               \
        for (int j = 0; j < 64; j++) { float c = (h)[j] - mu; var += c * c; } \
        var *= (1.0f / 64.0f);                                          \
        float inv = rsqrtf(var + 1e-5f);                                \
        _Pragma("unroll")                                               \
        for (int j = 0; j < 64; j++) {                                  \
            float v = ((h)[j] - mu) * inv * smem[(GO) + j] + smem[(BO) + j]; \
            (h)[j] = gelu_exact(v);                                     \
        }                                                               \
    } while (0)

__global__ __launch_bounds__(TPB)
void fused_kernel(
    const float* __restrict__ metadata, const float* __restrict__ prot,
    const float* __restrict__ age,      const float* __restrict__ maskp,
    const float* __restrict__ eW1, const float* __restrict__ eb1,
    const float* __restrict__ eg1, const float* __restrict__ eB1,
    const float* __restrict__ eW2, const float* __restrict__ eb2,
    const float* __restrict__ eg2, const float* __restrict__ eB2,
    const float* __restrict__ eW3, const float* __restrict__ eb3,
    const float* __restrict__ fW1, const float* __restrict__ fb1,
    const float* __restrict__ fW2, const float* __restrict__ fb2,
    const float* __restrict__ fW3, const float* __restrict__ fb3,
    float* __restrict__ out_latent, float* __restrict__ out_logprob,
    int B, int T)
{
    extern __shared__ __align__(16) float smem[];
    const int tid = threadIdx.x;
    const long long row = (long long)blockIdx.x * TPB + tid;
    const bool valid = (row < (long long)B);
    const long long r = valid ? row : 0;

    // ---- stage encoder weights ----
    for (int i = tid; i < 1408; i += TPB) smem[OW1 + i] = eW1[i];
    for (int i = tid; i < 4096; i += TPB) smem[OW2 + i] = eW2[i];
    for (int i = tid; i < 2048; i += TPB) smem[OW3 + i] = eW3[i];
    if (tid < 64) {
        smem[OB1 + tid] = eb1[tid]; smem[OG1 + tid] = eg1[tid]; smem[OBB1 + tid] = eB1[tid];
        smem[OB2 + tid] = eb2[tid]; smem[OG2 + tid] = eg2[tid]; smem[OBB2 + tid] = eB2[tid];
    }
    if (tid < 32) smem[OB3 + tid] = eb3[tid];

    // ---- stage inputs into per-thread work columns ----
#pragma unroll
    for (int i = 0; i < 11; i++) {
        smem[WORKOFF + i * TPB + tid]        = metadata[r * 11 + i];
        smem[WORKOFF + (11 + i) * TPB + tid] = maskp[r * 11 + i];
    }
    __syncthreads();

    float acc[64];

    // ---- GEMM1: (22) -> (64) ----
#pragma unroll
    for (int j = 0; j < 64; j++) acc[j] = smem[OB1 + j];
#pragma unroll 2
    for (int i = 0; i < 22; i++) {
        float xi = smem[WORKOFF + i * TPB + tid];
        const float4* wr = reinterpret_cast<const float4*>(&smem[OW1 + i * 64]);
#pragma unroll
        for (int j = 0; j < 16; j++) {
            float4 w4 = wr[j];
            acc[4 * j + 0] += xi * w4.x; acc[4 * j + 1] += xi * w4.y;
            acc[4 * j + 2] += xi * w4.z; acc[4 * j + 3] += xi * w4.w;
        }
    }
    LN_GELU(acc, OG1, OBB1);
#pragma unroll
    for (int j = 0; j < 64; j++) smem[WORKOFF + j * TPB + tid] = acc[j];

    // ---- GEMM2: (64) -> (64) ----
#pragma unroll
    for (int j = 0; j < 64; j++) acc[j] = smem[OB2 + j];
#pragma unroll 2
    for (int i = 0; i < 64; i++) {
        float xi = smem[WORKOFF + i * TPB + tid];
        const float4* wr = reinterpret_cast<const float4*>(&smem[OW2 + i * 64]);
#pragma unroll
        for (int j = 0; j < 16; j++) {
            float4 w4 = wr[j];
            acc[4 * j + 0] += xi * w4.x; acc[4 * j + 1] += xi * w4.y;
            acc[4 * j + 2] += xi * w4.z; acc[4 * j + 3] += xi * w4.w;
        }
    }
    LN_GELU(acc, OG2, OBB2);
#pragma unroll
    for (int j = 0; j < 64; j++) smem[WORKOFF + j * TPB + tid] = acc[j];

    // ---- GEMM3: (64) -> (32) latent ----
    float lat[32];
#pragma unroll
    for (int j = 0; j < 32; j++) lat[j] = smem[OB3 + j];
#pragma unroll 2
    for (int i = 0; i < 64; i++) {
        float xi = smem[WORKOFF + i * TPB + tid];
        const float4* wr = reinterpret_cast<const float4*>(&smem[OW3 + i * 32]);
#pragma unroll
        for (int j = 0; j < 8; j++) {
            float4 w4 = wr[j];
            lat[4 * j + 0] += xi * w4.x; lat[4 * j + 1] += xi * w4.y;
            lat[4 * j + 2] += xi * w4.z; lat[4 * j + 3] += xi * w4.w;
        }
    }
    if (valid) {
        float4* lp4 = reinterpret_cast<float4*>(out_latent + row * 32);
#pragma unroll
        for (int q = 0; q < 8; q++)
            lp4[q] = make_float4(lat[4 * q], lat[4 * q + 1], lat[4 * q + 2], lat[4 * q + 3]);
    }
#pragma unroll
    for (int j = 0; j < 32; j++) smem[CTXOFF + j * TPB + tid] = lat[j];
    smem[CTXOFF + 32 * TPB + tid] = prot[r];

    // ---- flow transforms ----
    float z = age[r];
    float ladj = 0.0f;

    for (int t = 0; t < T; t++) {
        __syncthreads();  // previous weight region fully consumed
        const float* w1t = fW1 + (long long)t * 2112;
        const float* w2t = fW2 + (long long)t * 4096;
        const float* w3t = fW3 + (long long)t * 1472;
        for (int i = tid; i < 2112; i += TPB) smem[FW1 + i] = w1t[i];
        for (int i = tid; i < 4096; i += TPB) smem[FW2 + i] = w2t[i];
        for (int i = tid; i < 1472; i += TPB) {
            int rr = i / 23, cc = i - rr * 23;
            smem[FW3 + rr * 24 + cc] = w3t[i];
        }
        if (tid < 64) {
            smem[FB1 + tid] = fb1[t * 64 + tid];
            smem[FB2 + tid] = fb2[t * 64 + tid];
            smem[FW3 + tid * 24 + 23] = 0.0f;   // pad column
        }
        if (tid < 23) smem[FB3 + tid] = fb3[t * 23 + tid];
        __syncthreads();

        // p1 = relu(ctx @ W1 + b1)
#pragma unroll
        for (int j = 0; j < 64; j++) acc[j] = smem[FB1 + j];
#pragma unroll 2
        for (int i = 0; i < 33; i++) {
            float xi = smem[CTXOFF + i * TPB + tid];
            const float4* wr = reinterpret_cast<const float4*>(&smem[FW1 + i * 64]);
#pragma unroll
            for (int j = 0; j < 16; j++) {
                float4 w4 = wr[j];
                acc[4 * j + 0] += xi * w4.x; acc[4 * j + 1] += xi * w4.y;
                acc[4 * j + 2] += xi * w4.z; acc[4 * j + 3] += xi * w4.w;
            }
        }
#pragma unroll
        for (int j = 0; j < 64; j++) smem[WORKOFF + j * TPB + tid] = fmaxf(acc[j], 0.0f);

        // p2 = relu(p1 @ W2 + b2)
#pragma unroll
        for (int j = 0; j < 64; j++) acc[j] = smem[FB2 + j];
#pragma unroll 2
        for (int i = 0; i < 64; i++) {
            float xi = smem[WORKOFF + i * TPB + tid];
            const float4* wr = reinterpret_cast<const float4*>(&smem[FW2 + i * 64]);
#pragma unroll
            for (int j = 0; j < 16; j++) {
                float4 w4 = wr[j];
                acc[4 * j + 0] += xi * w4.x; acc[4 * j + 1] += xi * w4.y;
                acc[4 * j + 2] += xi * w4.z; acc[4 * j + 3] += xi * w4.w;
            }
        }
#pragma unroll
        for (int j = 0; j < 64; j++) smem[WORKOFF + j * TPB + tid] = fmaxf(acc[j], 0.0f);

        // p3 = p2 @ W3 + b3   (23 outputs, padded to 24)
        float s3[24];
#pragma unroll
        for (int j = 0; j < 23; j++) s3[j] = smem[FB3 + j];
        s3[23] = 0.0f;
#pragma unroll 2
        for (int i = 0; i < 64; i++) {
            float xi = smem[WORKOFF + i * TPB + tid];
            const float4* wr = reinterpret_cast<const float4*>(&smem[FW3 + i * 24]);
#pragma unroll
            for (int j = 0; j < 6; j++) {
                float4 w4 = wr[j];
                s3[4 * j + 0] += xi * w4.x; s3[4 * j + 1] += xi * w4.y;
                s3[4 * j + 2] += xi * w4.z; s3[4 * j + 3] += xi * w4.w;
            }
        }

        // ---- rational-quadratic spline (K = 8 bins) ----
        {
            float w8[8], h8[8];
#pragma unroll
            for (int m = 0; m < 8; m++) { w8[m] = s3[m]; h8[m] = s3[8 + m]; }

            float mw = w8[0], mh = h8[0];
#pragma unroll
            for (int m = 1; m < 8; m++) { mw = fmaxf(mw, w8[m]); mh = fmaxf(mh, h8[m]); }
            float sw = 0.0f, sh = 0.0f;
#pragma unroll
            for (int m = 0; m < 8; m++) {
                w8[m] = expf(w8[m] - mw); sw += w8[m];
                h8[m] = expf(h8[m] - mh); sh += h8[m];
            }
            float scw = (2.0f * RQS_BOUND) / sw;
            float sch = (2.0f * RQS_BOUND) / sh;

            float xs[9], ys[9], ds[9];
            xs[0] = -RQS_BOUND; ys[0] = -RQS_BOUND;
            float cw = 0.0f, ch = 0.0f;
#pragma unroll
            for (int m = 0; m < 8; m++) {
                cw += w8[m] * scw; xs[m + 1] = -RQS_BOUND + cw;
                ch += h8[m] * sch; ys[m + 1] = -RQS_BOUND + ch;
            }
            ds[0] = 1.0f; ds[8] = 1.0f;
#pragma unroll
            for (int m = 0; m < 7; m++) ds[m + 1] = softplusf(s3[16 + m]);

            bool inside = (z > -RQS_BOUND) && (z < RQS_BOUND);
            float xc = fminf(fmaxf(z, -RQS_BOUND), RQS_BOUND);

            int k = -1;
#pragma unroll
            for (int m = 0; m < 8; m++) k += (xc >= xs[m]) ? 1 : 0;
            k = min(max(k, 0), 7);

            float x0 = xs[0], x1 = xs[1], y0 = ys[0], y1 = ys[1], d0 = ds[0], d1 = ds[1];
#pragma unroll
            for (int m = 1; m < 8; m++) {
                if (k == m) { x0 = xs[m]; x1 = xs[m + 1]; y0 = ys[m]; y1 = ys[m + 1]; d0 = ds[m]; d1 = ds[m + 1]; }
            }

            float wk = x1 - x0, hk = y1 - y0;
            float sk = hk / wk;
            float xi = (xc - x0) / wk;
            float om = 1.0f - xi;
            float den = sk + (d0 + d1 - 2.0f * sk) * xi * om;
            float yin = y0 + hk * (sk * xi * xi + d0 * xi * om) / den;
            float ldin = 2.0f * logf(sk)
                       + logf(d1 * xi * xi + 2.0f * sk * xi * om + d0 * om * om)
                       - 2.0f * logf(den);
            if (inside) { z = yin; ladj += ldin; }
        }
    }

    float lp = -0.5f * z * z + NEG_HALF_LOG_2PI + ladj;
    if (valid) out_logprob[row] = lp;

    // ---- deterministic block reduction for nll ----
    __syncthreads();
    double* sd = reinterpret_cast<double*>(smem);
    sd[tid] = valid ? (double)lp : 0.0;
    __syncthreads();
#pragma unroll
    for (int s = TPB / 2; s > 0; s >>= 1) {
        if (tid < s) sd[tid] += sd[tid + s];
        __syncthreads();
    }
    if (tid == 0) g_partial[blockIdx.x] = sd[0];
}

__global__ void nll_kernel(float* __restrict__ out_nll, int nblocks, double invB)
{
    __shared__ double sd[256];
    double s = 0.0;
    for (int i = threadIdx.x; i < nblocks; i += 256) s += g_partial[i];
    sd[threadIdx.x] = s;
    __syncthreads();
    for (int st = 128; st > 0; st >>= 1) {
        if (threadIdx.x < st) sd[threadIdx.x] += sd[threadIdx.x + st];
        __syncthreads();
    }
    if (threadIdx.x == 0) out_nll[0] = (float)(-sd[0] * invB);
}

extern "C" void kernel_launch(void* const* d_in, const int* in_sizes, int n_in,
                              void* d_out, int out_size)
{
    const float* metadata = (const float*)d_in[0];
    const float* prot     = (const float*)d_in[1];
    const float* age      = (const float*)d_in[2];
    const float* maskp    = (const float*)d_in[3];
    const float* eW1 = (const float*)d_in[4];
    const float* eb1 = (const float*)d_in[5];
    const float* eg1 = (const float*)d_in[6];
    const float* eB1 = (const float*)d_in[7];
    const float* eW2 = (const float*)d_in[8];
    const float* eb2 = (const float*)d_in[9];
    const float* eg2 = (const float*)d_in[10];
    const float* eB2 = (const float*)d_in[11];
    const float* eW3 = (const float*)d_in[12];
    const float* eb3 = (const float*)d_in[13];
    const float* fW1 = (const float*)d_in[14];
    const float* fb1 = (const float*)d_in[15];
    const float* fW2 = (const float*)d_in[16];
    const float* fb2 = (const float*)d_in[17];
    const float* fW3 = (const float*)d_in[18];
    const float* fb3 = (const float*)d_in[19];

    const int B = in_sizes[1];              // prot has B elements
    const int T = in_sizes[15] / 64;        // flow_b1 is (T, 64)

    float* out         = (float*)d_out;
    float* out_latent  = out;
    float* out_logprob = out + (size_t)B * 32;
    float* out_nll     = out + (size_t)B * 33;

    int nb = (B + TPB - 1) / TPB;
    size_t shmem = (size_t)SMEM_FLOATS * sizeof(float);
    cudaFuncSetAttribute(fused_kernel, cudaFuncAttributeMaxDynamicSharedMemorySize, (int)shmem);

    fused_kernel<<<nb, TPB, shmem>>>(
        metadata, prot, age, maskp,
        eW1, eb1, eg1, eB1, eW2, eb2, eg2, eB2, eW3, eb3,
        fW1, fb1, fW2, fb2, fW3, fb3,
        out_latent, out_logprob, B, T);

    nll_kernel<<<1, 256>>>(out_nll, nb, 1.0 / (double)B);
}

// round 7
// speedup vs baseline: 1.0413x; 1.0413x over previous
#include <cuda_runtime.h>
#include <math.h>

#define TPB 256
#define RQS_BOUND 5.0f
#define NEG_HALF_LOG_2PI (-0.9189385332046727f)

typedef unsigned long long u64;

// ---- shared memory layout (float offsets) ----
#define OW1   0      // enc_W1 22x64
#define OB1   1408
#define OG1   1472
#define OBB1  1536
#define OW2   1600   // enc_W2 64x64
#define OB2   5696
#define OG2   5760
#define OBB2  5824
#define OW3   5888   // enc_W3 64x32
#define OB3   7936   // 32
// flow phase overlays the same region
#define FW1   0      // 33x64 = 2112
#define FB1   2112   // 64
#define FW2   2176   // 64x64 = 4096
#define FB2   6272   // 64
#define FW3   6336   // 64x24 (padded from 23) = 1536
#define FB3   7872   // 23 (+1 pad)
#define CTXOFF  8064            // 33 * TPB
#define WORKOFF (8064 + 33*TPB) // 64 * TPB
#define SMEM_FLOATS (WORKOFF + 64*TPB)

__device__ double g_partial[16384];

// ---- packed f32x2 helpers (sm_103a FFMA2 path, PTX-only) ----
static __device__ __forceinline__ u64 pack2(float lo, float hi) {
    u64 r; asm("mov.b64 %0, {%1, %2};" : "=l"(r) : "f"(lo), "f"(hi)); return r;
}
static __device__ __forceinline__ float lo2(u64 v) { return __uint_as_float((unsigned)v); }
static __device__ __forceinline__ float hi2(u64 v) { return __uint_as_float((unsigned)(v >> 32)); }
static __device__ __forceinline__ void ffma2(u64& d, u64 a, u64 b) {
    asm("fma.rn.f32x2 %0, %1, %2, %3;" : "=l"(d) : "l"(a), "l"(b), "l"(d));
}
static __device__ __forceinline__ u64 add2(u64 a, u64 b) {
    u64 r; asm("add.rn.f32x2 %0, %1, %2;" : "=l"(r) : "l"(a), "l"(b)); return r;
}

static __device__ __forceinline__ float softplusf(float x) {
    return fmaxf(x, 0.0f) + log1pf(__expf(-fabsf(x)));
}
static __device__ __forceinline__ float gelu_exact(float x) {
    return x * normcdff(x);
}

// packed GEMM: NIN inputs (from smem work columns) -> 64 outputs in acc2[32]
#define GEMM64(NIN, WOFF, BOFF, SRCOFF)                                       \
    do {                                                                      \
        const u64* bp = reinterpret_cast<const u64*>(&smem[(BOFF)]);          \
        _Pragma("unroll")                                                     \
        for (int j = 0; j < 32; j++) acc2[j] = bp[j];                         \
        _Pragma("unroll 4")                                                   \
        for (int i = 0; i < (NIN); i++) {                                     \
            float xi = smem[(SRCOFF) + i * TPB + tid];                        \
            u64 xi2 = pack2(xi, xi);                                          \
            const ulonglong2* wr =                                            \
                reinterpret_cast<const ulonglong2*>(&smem[(WOFF) + i * 64]);  \
            _Pragma("unroll")                                                 \
            for (int j = 0; j < 16; j++) {                                    \
                ulonglong2 w = wr[j];                                         \
                ffma2(acc2[2 * j],     xi2, w.x);                             \
                ffma2(acc2[2 * j + 1], xi2, w.y);                             \
            }                                                                 \
        }                                                                     \
    } while (0)

// LN (over 64 packed in acc2[32]) + exact GELU; writes scalars to WORK
#define LN_GELU_STORE(GO, BO)                                                 \
    do {                                                                      \
        u64 s = acc2[0];                                                      \
        _Pragma("unroll")                                                     \
        for (int j = 1; j < 32; j++) s = add2(s, acc2[j]);                    \
        float mu = (lo2(s) + hi2(s)) * (1.0f / 64.0f);                        \
        float var = 0.0f;                                                     \
        _Pragma("unroll")                                                     \
        for (int j = 0; j < 32; j++) {                                        \
            float c0 = lo2(acc2[j]) - mu, c1 = hi2(acc2[j]) - mu;             \
            var += c0 * c0 + c1 * c1;                                         \
        }                                                                     \
        var *= (1.0f / 64.0f);                                                \
        float inv = rsqrtf(var + 1e-5f);                                      \
        _Pragma("unroll")                                                     \
        for (int j = 0; j < 32; j++) {                                        \
            float v0 = (lo2(acc2[j]) - mu) * inv * smem[(GO) + 2*j]     + smem[(BO) + 2*j];     \
            float v1 = (hi2(acc2[j]) - mu) * inv * smem[(GO) + 2*j + 1] + smem[(BO) + 2*j + 1]; \
            smem[WORKOFF + (2*j) * TPB + tid]     = gelu_exact(v0);           \
            smem[WORKOFF + (2*j + 1) * TPB + tid] = gelu_exact(v1);           \
        }                                                                     \
    } while (0)

__global__ __launch_bounds__(TPB)
void fused_kernel(
    const float* __restrict__ metadata, const float* __restrict__ prot,
    const float* __restrict__ age,      const float* __restrict__ maskp,
    const float* __restrict__ eW1, const float* __restrict__ eb1,
    const float* __restrict__ eg1, const float* __restrict__ eB1,
    const float* __restrict__ eW2, const float* __restrict__ eb2,
    const float* __restrict__ eg2, const float* __restrict__ eB2,
    const float* __restrict__ eW3, const float* __restrict__ eb3,
    const float* __restrict__ fW1, const float* __restrict__ fb1,
    const float* __restrict__ fW2, const float* __restrict__ fb2,
    const float* __restrict__ fW3, const float* __restrict__ fb3,
    float* __restrict__ out_latent, float* __restrict__ out_logprob,
    int B, int T)
{
    extern __shared__ __align__(16) float smem[];
    const int tid = threadIdx.x;
    const long long row = (long long)blockIdx.x * TPB + tid;
    const bool valid = (row < (long long)B);
    const long long r = valid ? row : 0;

    // ---- stage encoder weights ----
    for (int i = tid; i < 1408; i += TPB) smem[OW1 + i] = eW1[i];
    for (int i = tid; i < 4096; i += TPB) smem[OW2 + i] = eW2[i];
    for (int i = tid; i < 2048; i += TPB) smem[OW3 + i] = eW3[i];
    if (tid < 64) {
        smem[OB1 + tid] = eb1[tid]; smem[OG1 + tid] = eg1[tid]; smem[OBB1 + tid] = eB1[tid];
        smem[OB2 + tid] = eb2[tid]; smem[OG2 + tid] = eg2[tid]; smem[OBB2 + tid] = eB2[tid];
    }
    if (tid < 32) smem[OB3 + tid] = eb3[tid];

    // ---- stage inputs into per-thread work columns ----
#pragma unroll
    for (int i = 0; i < 11; i++) {
        smem[WORKOFF + i * TPB + tid]        = metadata[r * 11 + i];
        smem[WORKOFF + (11 + i) * TPB + tid] = maskp[r * 11 + i];
    }
    __syncthreads();

    u64 acc2[32];

    // ---- GEMM1: 22 -> 64, LN + GELU ----
    GEMM64(22, OW1, OB1, WORKOFF);
    LN_GELU_STORE(OG1, OBB1);

    // ---- GEMM2: 64 -> 64, LN + GELU ----
    GEMM64(64, OW2, OB2, WORKOFF);
    LN_GELU_STORE(OG2, OBB2);

    // ---- GEMM3: 64 -> 32 (latent) ----
    {
        u64 lat2[16];
        const u64* bp = reinterpret_cast<const u64*>(&smem[OB3]);
#pragma unroll
        for (int j = 0; j < 16; j++) lat2[j] = bp[j];
#pragma unroll 4
        for (int i = 0; i < 64; i++) {
            float xi = smem[WORKOFF + i * TPB + tid];
            u64 xi2 = pack2(xi, xi);
            const ulonglong2* wr = reinterpret_cast<const ulonglong2*>(&smem[OW3 + i * 32]);
#pragma unroll
            for (int j = 0; j < 8; j++) {
                ulonglong2 w = wr[j];
                ffma2(lat2[2 * j],     xi2, w.x);
                ffma2(lat2[2 * j + 1], xi2, w.y);
            }
        }
        if (valid) {
            float4* lp4 = reinterpret_cast<float4*>(out_latent + row * 32);
#pragma unroll
            for (int q = 0; q < 8; q++)
                lp4[q] = make_float4(lo2(lat2[2 * q]), hi2(lat2[2 * q]),
                                     lo2(lat2[2 * q + 1]), hi2(lat2[2 * q + 1]));
        }
#pragma unroll
        for (int j = 0; j < 16; j++) {
            smem[CTXOFF + (2 * j) * TPB + tid]     = lo2(lat2[j]);
            smem[CTXOFF + (2 * j + 1) * TPB + tid] = hi2(lat2[j]);
        }
        smem[CTXOFF + 32 * TPB + tid] = prot[r];
    }

    // ---- flow transforms ----
    float z = age[r];
    float ladj = 0.0f;

    for (int t = 0; t < T; t++) {
        __syncthreads();
        const float* w1t = fW1 + (long long)t * 2112;
        const float* w2t = fW2 + (long long)t * 4096;
        const float* w3t = fW3 + (long long)t * 1472;
        for (int i = tid; i < 2112; i += TPB) smem[FW1 + i] = w1t[i];
        for (int i = tid; i < 4096; i += TPB) smem[FW2 + i] = w2t[i];
        for (int i = tid; i < 1472; i += TPB) {
            int rr = i / 23, cc = i - rr * 23;
            smem[FW3 + rr * 24 + cc] = w3t[i];
        }
        if (tid < 64) {
            smem[FB1 + tid] = fb1[t * 64 + tid];
            smem[FB2 + tid] = fb2[t * 64 + tid];
            smem[FW3 + tid * 24 + 23] = 0.0f;
        }
        if (tid < 24) smem[FB3 + tid] = (tid < 23) ? fb3[t * 23 + tid] : 0.0f;
        __syncthreads();

        // p1 = relu(ctx @ W1 + b1)
        GEMM64(33, FW1, FB1, CTXOFF);
#pragma unroll
        for (int j = 0; j < 32; j++) {
            smem[WORKOFF + (2 * j) * TPB + tid]     = fmaxf(lo2(acc2[j]), 0.0f);
            smem[WORKOFF + (2 * j + 1) * TPB + tid] = fmaxf(hi2(acc2[j]), 0.0f);
        }

        // p2 = relu(p1 @ W2 + b2)
        GEMM64(64, FW2, FB2, WORKOFF);
#pragma unroll
        for (int j = 0; j < 32; j++) {
            smem[WORKOFF + (2 * j) * TPB + tid]     = fmaxf(lo2(acc2[j]), 0.0f);
            smem[WORKOFF + (2 * j + 1) * TPB + tid] = fmaxf(hi2(acc2[j]), 0.0f);
        }

        // p3 = p2 @ W3 + b3   (23 outputs, padded to 24)
        float s3[24];
        {
            u64 s32[12];
            const u64* bp = reinterpret_cast<const u64*>(&smem[FB3]);
#pragma unroll
            for (int j = 0; j < 12; j++) s32[j] = bp[j];
#pragma unroll 4
            for (int i = 0; i < 64; i++) {
                float xi = smem[WORKOFF + i * TPB + tid];
                u64 xi2 = pack2(xi, xi);
                const ulonglong2* wr = reinterpret_cast<const ulonglong2*>(&smem[FW3 + i * 24]);
#pragma unroll
                for (int j = 0; j < 6; j++) {
                    ulonglong2 w = wr[j];
                    ffma2(s32[2 * j],     xi2, w.x);
                    ffma2(s32[2 * j + 1], xi2, w.y);
                }
            }
#pragma unroll
            for (int j = 0; j < 12; j++) { s3[2 * j] = lo2(s32[j]); s3[2 * j + 1] = hi2(s32[j]); }
        }

        // ---- rational-quadratic spline (K = 8 bins) ----
        {
            float w8[8], h8[8];
#pragma unroll
            for (int m = 0; m < 8; m++) { w8[m] = s3[m]; h8[m] = s3[8 + m]; }

            float mw = w8[0], mh = h8[0];
#pragma unroll
            for (int m = 1; m < 8; m++) { mw = fmaxf(mw, w8[m]); mh = fmaxf(mh, h8[m]); }
            float sw = 0.0f, sh = 0.0f;
#pragma unroll
            for (int m = 0; m < 8; m++) {
                w8[m] = __expf(w8[m] - mw); sw += w8[m];
                h8[m] = __expf(h8[m] - mh); sh += h8[m];
            }
            float scw = (2.0f * RQS_BOUND) / sw;
            float sch = (2.0f * RQS_BOUND) / sh;

            float xs[9], ys[9], ds[9];
            xs[0] = -RQS_BOUND; ys[0] = -RQS_BOUND;
            float cw = 0.0f, ch = 0.0f;
#pragma unroll
            for (int m = 0; m < 8; m++) {
                cw += w8[m] * scw; xs[m + 1] = -RQS_BOUND + cw;
                ch += h8[m] * sch; ys[m + 1] = -RQS_BOUND + ch;
            }
            ds[0] = 1.0f; ds[8] = 1.0f;
#pragma unroll
            for (int m = 0; m < 7; m++) ds[m + 1] = softplusf(s3[16 + m]);

            bool inside = (z > -RQS_BOUND) && (z < RQS_BOUND);
            float xc = fminf(fmaxf(z, -RQS_BOUND), RQS_BOUND);

            int k = -1;
#pragma unroll
            for (int m = 0; m < 8; m++) k += (xc >= xs[m]) ? 1 : 0;
            k = min(max(k, 0), 7);

            float x0 = xs[0], x1 = xs[1], y0 = ys[0], y1 = ys[1], d0 = ds[0], d1 = ds[1];
#pragma unroll
            for (int m = 1; m < 8; m++) {
                if (k == m) { x0 = xs[m]; x1 = xs[m + 1]; y0 = ys[m]; y1 = ys[m + 1]; d0 = ds[m]; d1 = ds[m + 1]; }
            }

            float wk = x1 - x0, hk = y1 - y0;
            float sk = hk / wk;
            float xi = (xc - x0) / wk;
            float om = 1.0f - xi;
            float den = sk + (d0 + d1 - 2.0f * sk) * xi * om;
            float yin = y0 + hk * (sk * xi * xi + d0 * xi * om) / den;
            float ldin = 2.0f * __logf(sk)
                       + __logf(d1 * xi * xi + 2.0f * sk * xi * om + d0 * om * om)
                       - 2.0f * __logf(den);
            if (inside) { z = yin; ladj += ldin; }
        }
    }

    float lp = -0.5f * z * z + NEG_HALF_LOG_2PI + ladj;
    if (valid) out_logprob[row] = lp;

    // ---- deterministic block reduction for nll ----
    __syncthreads();
    double* sd = reinterpret_cast<double*>(smem);
    sd[tid] = valid ? (double)lp : 0.0;
    __syncthreads();
#pragma unroll
    for (int s = TPB / 2; s > 0; s >>= 1) {
        if (tid < s) sd[tid] += sd[tid + s];
        __syncthreads();
    }
    if (tid == 0) g_partial[blockIdx.x] = sd[0];
}

__global__ void nll_kernel(float* __restrict__ out_nll, int nblocks, double invB)
{
    __shared__ double sd[256];
    double s = 0.0;
    for (int i = threadIdx.x; i < nblocks; i += 256) s += g_partial[i];
    sd[threadIdx.x] = s;
    __syncthreads();
    for (int st = 128; st > 0; st >>= 1) {
        if (threadIdx.x < st) sd[threadIdx.x] += sd[threadIdx.x + st];
        __syncthreads();
    }
    if (threadIdx.x == 0) out_nll[0] = (float)(-sd[0] * invB);
}

extern "C" void kernel_launch(void* const* d_in, const int* in_sizes, int n_in,
                              void* d_out, int out_size)
{
    const float* metadata = (const float*)d_in[0];
    const float* prot     = (const float*)d_in[1];
    const float* age      = (const float*)d_in[2];
    const float* maskp    = (const float*)d_in[3];
    const float* eW1 = (const float*)d_in[4];
    const float* eb1 = (const float*)d_in[5];
    const float* eg1 = (const float*)d_in[6];
    const float* eB1 = (const float*)d_in[7];
    const float* eW2 = (const float*)d_in[8];
    const float* eb2 = (const float*)d_in[9];
    const float* eg2 = (const float*)d_in[10];
    const float* eB2 = (const float*)d_in[11];
    const float* eW3 = (const float*)d_in[12];
    const float* eb3 = (const float*)d_in[13];
    const float* fW1 = (const float*)d_in[14];
    const float* fb1 = (const float*)d_in[15];
    const float* fW2 = (const float*)d_in[16];
    const float* fb2 = (const float*)d_in[17];
    const float* fW3 = (const float*)d_in[18];
    const float* fb3 = (const float*)d_in[19];

    const int B = in_sizes[1];
    const int T = in_sizes[15] / 64;

    float* out         = (float*)d_out;
    float* out_latent  = out;
    float* out_logprob = out + (size_t)B * 32;
    float* out_nll     = out + (size_t)B * 33;

    int nb = (B + TPB - 1) / TPB;
    size_t shmem = (size_t)SMEM_FLOATS * sizeof(float);
    cudaFuncSetAttribute(fused_kernel, cudaFuncAttributeMaxDynamicSharedMemorySize, (int)shmem);

    fused_kernel<<<nb, TPB, shmem>>>(
        metadata, prot, age, maskp,
        eW1, eb1, eg1, eB1, eW2, eb2, eg2, eB2, eW3, eb3,
        fW1, fb1, fW2, fb2, fW3, fb3,
        out_latent, out_logprob, B, T);

    nll_kernel<<<1, 256>>>(out_nll, nb, 1.0 / (double)B);
}

// round 8
// speedup vs baseline: 1.3921x; 1.3369x over previous
#include <cuda_runtime.h>
#include <math.h>

#define TPB 192
#define RQS_BOUND 5.0f
#define NEG_HALF_LOG_2PI (-0.9189385332046727f)

typedef unsigned long long u64;

// ---- shared memory layout (float offsets) ----
#define OW1   0      // enc_W1 22x64
#define OB1   1408
#define OG1   1472
#define OBB1  1536
#define OW2   1600   // enc_W2 64x64
#define OB2   5696
#define OG2   5760
#define OBB2  5824
#define OW3   5888   // enc_W3 64x32
#define OB3   7936   // 32
// flow phase overlays the same region
#define FW1   0      // 33x64 = 2112
#define FB1   2112   // 64
#define FW2   2176   // 64x64 = 4096
#define FB2   6272   // 64
#define FW3   6336   // 64x24 (padded from 23) = 1536
#define FB3   7872   // 23 (+1 pad)
#define CTXOFF  8064            // 33 * TPB
#define WORKOFF (8064 + 33*TPB) // 64 * TPB
#define SMEM_FLOATS (WORKOFF + 64*TPB)

__device__ double g_partial[16384];
__device__ unsigned int g_done;   // zero-init at load; last CTA resets to 0 each launch

// ---- packed f32x2 helpers (sm_103a FFMA2 path, PTX-only) ----
static __device__ __forceinline__ u64 pack2(float lo, float hi) {
    u64 r; asm("mov.b64 %0, {%1, %2};" : "=l"(r) : "f"(lo), "f"(hi)); return r;
}
static __device__ __forceinline__ float lo2(u64 v) { return __uint_as_float((unsigned)v); }
static __device__ __forceinline__ float hi2(u64 v) { return __uint_as_float((unsigned)(v >> 32)); }
static __device__ __forceinline__ void ffma2(u64& d, u64 a, u64 b) {
    asm("fma.rn.f32x2 %0, %1, %2, %3;" : "=l"(d) : "l"(a), "l"(b), "l"(d));
}
static __device__ __forceinline__ u64 add2(u64 a, u64 b) {
    u64 r; asm("add.rn.f32x2 %0, %1, %2;" : "=l"(r) : "l"(a), "l"(b)); return r;
}

static __device__ __forceinline__ float softplusf(float x) {
    // exp(-|x|) in (0,1], so log(1+e) has no cancellation; fast paths are safe
    return fmaxf(x, 0.0f) + __logf(1.0f + __expf(-fabsf(x)));
}
static __device__ __forceinline__ float gelu_exact(float x) {
    return x * normcdff(x);
}

// packed GEMM: NIN inputs (from smem work columns) -> 64 outputs in acc2[32]
#define GEMM64(NIN, WOFF, BOFF, SRCOFF)                                       \
    do {                                                                      \
        const u64* bp = reinterpret_cast<const u64*>(&smem[(BOFF)]);          \
        _Pragma("unroll")                                                     \
        for (int j = 0; j < 32; j++) acc2[j] = bp[j];                         \
        _Pragma("unroll 4")                                                   \
        for (int i = 0; i < (NIN); i++) {                                     \
            float xi = smem[(SRCOFF) + i * TPB + tid];                        \
            u64 xi2 = pack2(xi, xi);                                          \
            const ulonglong2* wr =                                            \
                reinterpret_cast<const ulonglong2*>(&smem[(WOFF) + i * 64]);  \
            _Pragma("unroll")                                                 \
            for (int j = 0; j < 16; j++) {                                    \
                ulonglong2 w = wr[j];                                         \
                ffma2(acc2[2 * j],     xi2, w.x);                             \
                ffma2(acc2[2 * j + 1], xi2, w.y);                             \
            }                                                                 \
        }                                                                     \
    } while (0)

// LN (over 64 packed in acc2[32]) + exact GELU; writes scalars to WORK
#define LN_GELU_STORE(GO, BO)                                                 \
    do {                                                                      \
        u64 s = acc2[0];                                                      \
        _Pragma("unroll")                                                     \
        for (int j = 1; j < 32; j++) s = add2(s, acc2[j]);                    \
        float mu = (lo2(s) + hi2(s)) * (1.0f / 64.0f);                        \
        float var = 0.0f;                                                     \
        _Pragma("unroll")                                                     \
        for (int j = 0; j < 32; j++) {                                        \
            float c0 = lo2(acc2[j]) - mu, c1 = hi2(acc2[j]) - mu;             \
            var += c0 * c0 + c1 * c1;                                         \
        }                                                                     \
        var *= (1.0f / 64.0f);                                                \
        float inv = rsqrtf(var + 1e-5f);                                      \
        _Pragma("unroll")                                                     \
        for (int j = 0; j < 32; j++) {                                        \
            float v0 = (lo2(acc2[j]) - mu) * inv * smem[(GO) + 2*j]     + smem[(BO) + 2*j];     \
            float v1 = (hi2(acc2[j]) - mu) * inv * smem[(GO) + 2*j + 1] + smem[(BO) + 2*j + 1]; \
            smem[WORKOFF + (2*j) * TPB + tid]     = gelu_exact(v0);           \
            smem[WORKOFF + (2*j + 1) * TPB + tid] = gelu_exact(v1);           \
        }                                                                     \
    } while (0)

__global__ __launch_bounds__(TPB, 2)
void fused_kernel(
    const float* __restrict__ metadata, const float* __restrict__ prot,
    const float* __restrict__ age,      const float* __restrict__ maskp,
    const float* __restrict__ eW1, const float* __restrict__ eb1,
    const float* __restrict__ eg1, const float* __restrict__ eB1,
    const float* __restrict__ eW2, const float* __restrict__ eb2,
    const float* __restrict__ eg2, const float* __restrict__ eB2,
    const float* __restrict__ eW3, const float* __restrict__ eb3,
    const float* __restrict__ fW1, const float* __restrict__ fb1,
    const float* __restrict__ fW2, const float* __restrict__ fb2,
    const float* __restrict__ fW3, const float* __restrict__ fb3,
    float* __restrict__ out_latent, float* __restrict__ out_logprob,
    float* __restrict__ out_nll, int B, int T, int nb, float invB)
{
    extern __shared__ __align__(16) float smem[];
    __shared__ int s_islast;
    const int tid = threadIdx.x;
    const long long row = (long long)blockIdx.x * TPB + tid;
    const bool valid = (row < (long long)B);
    const long long r = valid ? row : 0;

    // ---- stage encoder weights ----
    for (int i = tid; i < 1408; i += TPB) smem[OW1 + i] = eW1[i];
    for (int i = tid; i < 4096; i += TPB) smem[OW2 + i] = eW2[i];
    for (int i = tid; i < 2048; i += TPB) smem[OW3 + i] = eW3[i];
    if (tid < 64) {
        smem[OB1 + tid] = eb1[tid]; smem[OG1 + tid] = eg1[tid]; smem[OBB1 + tid] = eB1[tid];
        smem[OB2 + tid] = eb2[tid]; smem[OG2 + tid] = eg2[tid]; smem[OBB2 + tid] = eB2[tid];
    }
    if (tid < 32) smem[OB3 + tid] = eb3[tid];

    // ---- stage inputs into per-thread work columns ----
#pragma unroll
    for (int i = 0; i < 11; i++) {
        smem[WORKOFF + i * TPB + tid]        = metadata[r * 11 + i];
        smem[WORKOFF + (11 + i) * TPB + tid] = maskp[r * 11 + i];
    }
    __syncthreads();

    u64 acc2[32];

    // ---- GEMM1: 22 -> 64, LN + GELU ----
    GEMM64(22, OW1, OB1, WORKOFF);
    LN_GELU_STORE(OG1, OBB1);

    // ---- GEMM2: 64 -> 64, LN + GELU ----
    GEMM64(64, OW2, OB2, WORKOFF);
    LN_GELU_STORE(OG2, OBB2);

    // ---- GEMM3: 64 -> 32 (latent) ----
    {
        u64 lat2[16];
        const u64* bp = reinterpret_cast<const u64*>(&smem[OB3]);
#pragma unroll
        for (int j = 0; j < 16; j++) lat2[j] = bp[j];
#pragma unroll 4
        for (int i = 0; i < 64; i++) {
            float xi = smem[WORKOFF + i * TPB + tid];
            u64 xi2 = pack2(xi, xi);
            const ulonglong2* wr = reinterpret_cast<const ulonglong2*>(&smem[OW3 + i * 32]);
#pragma unroll
            for (int j = 0; j < 8; j++) {
                ulonglong2 w = wr[j];
                ffma2(lat2[2 * j],     xi2, w.x);
                ffma2(lat2[2 * j + 1], xi2, w.y);
            }
        }
        if (valid) {
            float4* lp4 = reinterpret_cast<float4*>(out_latent + row * 32);
#pragma unroll
            for (int q = 0; q < 8; q++)
                lp4[q] = make_float4(lo2(lat2[2 * q]), hi2(lat2[2 * q]),
                                     lo2(lat2[2 * q + 1]), hi2(lat2[2 * q + 1]));
        }
#pragma unroll
        for (int j = 0; j < 16; j++) {
            smem[CTXOFF + (2 * j) * TPB + tid]     = lo2(lat2[j]);
            smem[CTXOFF + (2 * j + 1) * TPB + tid] = hi2(lat2[j]);
        }
        smem[CTXOFF + 32 * TPB + tid] = prot[r];
    }

    // ---- flow transforms ----
    float z = age[r];
    float ladj = 0.0f;

    for (int t = 0; t < T; t++) {
        __syncthreads();
        const float* w1t = fW1 + (long long)t * 2112;
        const float* w2t = fW2 + (long long)t * 4096;
        const float* w3t = fW3 + (long long)t * 1472;
        for (int i = tid; i < 2112; i += TPB) smem[FW1 + i] = w1t[i];
        for (int i = tid; i < 4096; i += TPB) smem[FW2 + i] = w2t[i];
        for (int i = tid; i < 1472; i += TPB) {
            int rr = i / 23, cc = i - rr * 23;
            smem[FW3 + rr * 24 + cc] = w3t[i];
        }
        if (tid < 64) {
            smem[FB1 + tid] = fb1[t * 64 + tid];
            smem[FB2 + tid] = fb2[t * 64 + tid];
            smem[FW3 + tid * 24 + 23] = 0.0f;
        }
        if (tid < 24) smem[FB3 + tid] = (tid < 23) ? fb3[t * 23 + tid] : 0.0f;
        __syncthreads();

        // p1 = relu(ctx @ W1 + b1)
        GEMM64(33, FW1, FB1, CTXOFF);
#pragma unroll
        for (int j = 0; j < 32; j++) {
            smem[WORKOFF + (2 * j) * TPB + tid]     = fmaxf(lo2(acc2[j]), 0.0f);
            smem[WORKOFF + (2 * j + 1) * TPB + tid] = fmaxf(hi2(acc2[j]), 0.0f);
        }

        // p2 = relu(p1 @ W2 + b2)
        GEMM64(64, FW2, FB2, WORKOFF);
#pragma unroll
        for (int j = 0; j < 32; j++) {
            smem[WORKOFF + (2 * j) * TPB + tid]     = fmaxf(lo2(acc2[j]), 0.0f);
            smem[WORKOFF + (2 * j + 1) * TPB + tid] = fmaxf(hi2(acc2[j]), 0.0f);
        }

        // p3 = p2 @ W3 + b3   (23 outputs, padded to 24)
        float s3[24];
        {
            u64 s32[12];
            const u64* bp = reinterpret_cast<const u64*>(&smem[FB3]);
#pragma unroll
            for (int j = 0; j < 12; j++) s32[j] = bp[j];
#pragma unroll 4
            for (int i = 0; i < 64; i++) {
                float xi = smem[WORKOFF + i * TPB + tid];
                u64 xi2 = pack2(xi, xi);
                const ulonglong2* wr = reinterpret_cast<const ulonglong2*>(&smem[FW3 + i * 24]);
#pragma unroll
                for (int j = 0; j < 6; j++) {
                    ulonglong2 w = wr[j];
                    ffma2(s32[2 * j],     xi2, w.x);
                    ffma2(s32[2 * j + 1], xi2, w.y);
                }
            }
#pragma unroll
            for (int j = 0; j < 12; j++) { s3[2 * j] = lo2(s32[j]); s3[2 * j + 1] = hi2(s32[j]); }
        }

        // ---- rational-quadratic spline (K = 8 bins) ----
        {
            float w8[8], h8[8];
#pragma unroll
            for (int m = 0; m < 8; m++) { w8[m] = s3[m]; h8[m] = s3[8 + m]; }

            float mw = w8[0], mh = h8[0];
#pragma unroll
            for (int m = 1; m < 8; m++) { mw = fmaxf(mw, w8[m]); mh = fmaxf(mh, h8[m]); }
            float sw = 0.0f, sh = 0.0f;
#pragma unroll
            for (int m = 0; m < 8; m++) {
                w8[m] = __expf(w8[m] - mw); sw += w8[m];
                h8[m] = __expf(h8[m] - mh); sh += h8[m];
            }
            float scw = __fdividef(2.0f * RQS_BOUND, sw);
            float sch = __fdividef(2.0f * RQS_BOUND, sh);

            float xs[9], ys[9], ds[9];
            xs[0] = -RQS_BOUND; ys[0] = -RQS_BOUND;
            float cw = 0.0f, ch = 0.0f;
#pragma unroll
            for (int m = 0; m < 8; m++) {
                cw += w8[m] * scw; xs[m + 1] = -RQS_BOUND + cw;
                ch += h8[m] * sch; ys[m + 1] = -RQS_BOUND + ch;
            }
            ds[0] = 1.0f; ds[8] = 1.0f;
#pragma unroll
            for (int m = 0; m < 7; m++) ds[m + 1] = softplusf(s3[16 + m]);

            bool inside = (z > -RQS_BOUND) && (z < RQS_BOUND);
            float xc = fminf(fmaxf(z, -RQS_BOUND), RQS_BOUND);

            int k = -1;
#pragma unroll
            for (int m = 0; m < 8; m++) k += (xc >= xs[m]) ? 1 : 0;
            k = min(max(k, 0), 7);

            float x0 = xs[0], x1 = xs[1], y0 = ys[0], y1 = ys[1], d0 = ds[0], d1 = ds[1];
#pragma unroll
            for (int m = 1; m < 8; m++) {
                if (k == m) { x0 = xs[m]; x1 = xs[m + 1]; y0 = ys[m]; y1 = ys[m + 1]; d0 = ds[m]; d1 = ds[m + 1]; }
            }

            float wk = x1 - x0, hk = y1 - y0;
            float sk = __fdividef(hk, wk);
            float xi = __fdividef(xc - x0, wk);
            float om = 1.0f - xi;
            float den = sk + (d0 + d1 - 2.0f * sk) * xi * om;
            float yin = y0 + hk * __fdividef(sk * xi * xi + d0 * xi * om, den);
            float ldin = 2.0f * (__logf(sk) - __logf(den))
                       + __logf(d1 * xi * xi + 2.0f * sk * xi * om + d0 * om * om);
            if (inside) { z = yin; ladj += ldin; }
        }
    }

    float lp = -0.5f * z * z + NEG_HALF_LOG_2PI + ladj;
    if (valid) out_logprob[row] = lp;

    // ---- deterministic block reduction for nll partial ----
    __syncthreads();
    double* sd = reinterpret_cast<double*>(smem);
    sd[tid] = valid ? (double)lp : 0.0;
    __syncthreads();
    if (tid < 64) sd[tid] += sd[tid + 128];
    __syncthreads();
#pragma unroll
    for (int s = 64; s > 0; s >>= 1) {
        if (tid < s) sd[tid] += sd[tid + s];
        __syncthreads();
    }
    if (tid == 0) {
        g_partial[blockIdx.x] = sd[0];
        __threadfence();
        unsigned int ticket = atomicAdd(&g_done, 1u);
        s_islast = (ticket == (unsigned int)(nb - 1)) ? 1 : 0;
    }
    __syncthreads();

    // ---- last CTA reduces all partials (deterministic order per thread) ----
    if (s_islast) {
        double s = 0.0;
        for (int i = tid; i < nb; i += TPB) s += g_partial[i];
        sd[tid] = s;
        __syncthreads();
        if (tid < 64) sd[tid] += sd[tid + 128];
        __syncthreads();
#pragma unroll
        for (int st = 64; st > 0; st >>= 1) {
            if (tid < st) sd[tid] += sd[tid + st];
            __syncthreads();
        }
        if (tid == 0) {
            out_nll[0] = (float)(-sd[0] * (double)invB);
            g_done = 0;   // self-reset for next graph replay
        }
    }
}

extern "C" void kernel_launch(void* const* d_in, const int* in_sizes, int n_in,
                              void* d_out, int out_size)
{
    const float* metadata = (const float*)d_in[0];
    const float* prot     = (const float*)d_in[1];
    const float* age      = (const float*)d_in[2];
    const float* maskp    = (const float*)d_in[3];
    const float* eW1 = (const float*)d_in[4];
    const float* eb1 = (const float*)d_in[5];
    const float* eg1 = (const float*)d_in[6];
    const float* eB1 = (const float*)d_in[7];
    const float* eW2 = (const float*)d_in[8];
    const float* eb2 = (const float*)d_in[9];
    const float* eg2 = (const float*)d_in[10];
    const float* eB2 = (const float*)d_in[11];
    const float* eW3 = (const float*)d_in[12];
    const float* eb3 = (const float*)d_in[13];
    const float* fW1 = (const float*)d_in[14];
    const float* fb1 = (const float*)d_in[15];
    const float* fW2 = (const float*)d_in[16];
    const float* fb2 = (const float*)d_in[17];
    const float* fW3 = (const float*)d_in[18];
    const float* fb3 = (const float*)d_in[19];

    const int B = in_sizes[1];
    const int T = in_sizes[15] / 64;

    float* out         = (float*)d_out;
    float* out_latent  = out;
    float* out_logprob = out + (size_t)B * 32;
    float* out_nll     = out + (size_t)B * 33;

    int nb = (B + TPB - 1) / TPB;
    size_t shmem = (size_t)SMEM_FLOATS * sizeof(float);
    cudaFuncSetAttribute(fused_kernel, cudaFuncAttributeMaxDynamicSharedMemorySize, (int)shmem);

    fused_kernel<<<nb, TPB, shmem>>>(
        metadata, prot, age, maskp,
        eW1, eb1, eg1, eB1, eW2, eb2, eg2, eB2, eW3, eb3,
        fW1, fb1, fW2, fb2, fW3, fb3,
        out_latent, out_logprob, out_nll, B, T, nb, 1.0f / (float)B);
}